// round 9
// baseline (speedup 1.0000x reference)
#include <cuda_runtime.h>
#include <cstdint>

// out[b,h,w,:] = graph_lstm_output[b, slic[b,h,w]-1, :]
//   graph_lstm_output: [B=4, S=256, C=128] f32   (d_in[0])
//   slic_output:       [B=4, 512, 512] i32       (d_in[1])
//
// R3/R5/R8 all pin at 6.0 TB/s, dram_active=76% with 24% idle. Theory: the
// slic reads (4 MB, DRAM-sourced) trickle into the 512 MB write stream and
// force HBM read/write turnarounds. R9: prefetch slic+table into L2 first
// (they fit: 4.5 MB of 126 MB), making the main kernel's DRAM traffic
// write-only.

static constexpr int B = 4;
static constexpr int S = 256;
static constexpr int C = 128;                         // 32 float4 per row
static constexpr unsigned F4_PER_BATCH = 1u << 23;    // 2^18 pix * 32 f4
static constexpr int UNROLL = 4;
static constexpr unsigned CHUNK = F4_PER_BATCH / UNROLL;   // 2^21 f4
static constexpr unsigned THREADS_TOTAL = 1u << 23;        // 2^25 f4 / 4

// ---------------------------------------------------------------------------
// Kernel A: pull slic (4 MB) + table (0.5 MB) into L2 via prefetch.global.L2.
// One prefetch per 128 B line: 32768 (slic) + 4096 (table) = 36864 threads.
// ---------------------------------------------------------------------------
__global__ __launch_bounds__(256)
void l2_prefetch(const int* __restrict__ slic, const float* __restrict__ src)
{
    unsigned t = blockIdx.x * blockDim.x + threadIdx.x;
    if (t < 32768u) {
        const char* p = reinterpret_cast<const char*>(slic) + (size_t)t * 128;
        asm volatile("prefetch.global.L2 [%0];" :: "l"(p));
    } else {
        unsigned u = t - 32768u;   // 0..4095 table lines
        const char* p = reinterpret_cast<const char*>(src) + (size_t)u * 128;
        asm volatile("prefetch.global.L2 [%0];" :: "l"(p));
    }
}

// ---------------------------------------------------------------------------
// Kernel B: batch-local 4-way gather (R8 structure); slic loads now L2 hits.
// ---------------------------------------------------------------------------
__global__ __launch_bounds__(256)
void convert2image_l1(const float4* __restrict__ src,   // [B*S, 32] float4
                      const int*    __restrict__ slic,  // [B, 2^18]
                      float4*       __restrict__ out)   // [B, 2^18, 32]
{
    const unsigned t = blockIdx.x * blockDim.x + threadIdx.x;  // [0, 2^23)

    const unsigned b    = t >> 21;             // batch: 2^21 threads per batch
    const unsigned loc  = t & (CHUNK - 1u);    // local f4 base within batch
    const unsigned lane = loc & 31;

    const int*    sl = slic + (b << 18);
    const float4* tb = src  + (b << 13);       // this batch's 128 KB table
    float4*       ob = out  + (b << 23);

    // Phase 1: 4 independent slic loads (L2-resident after prefetch).
    const float4* rowp[UNROLL];
    #pragma unroll
    for (int i = 0; i < UNROLL; i++) {
        unsigned pix = (loc + (unsigned)i * CHUNK) >> 5;
        int seg = __ldg(&sl[pix]) - 1;         // 0-based segment, L2 hit
        rowp[i] = tb + (((unsigned)seg) << 5); // seg * 32 float4
    }

    // Phase 2: 4 independent gathers from the batch-local table
    // (L1-resident working set: 128 KB shared by all CTAs on the SM).
    float4 v[UNROLL];
    #pragma unroll
    for (int i = 0; i < UNROLL; i++)
        v[i] = __ldg(&rowp[i][lane]);

    // Phase 3: 4 coalesced streaming stores (write-once, evict-first).
    #pragma unroll
    for (int i = 0; i < UNROLL; i++)
        __stcs(&ob[loc + (unsigned)i * CHUNK], v[i]);
}

extern "C" void kernel_launch(void* const* d_in, const int* in_sizes, int n_in,
                              void* d_out, int out_size)
{
    const float4* src  = (const float4*)d_in[0];
    const int*    slic = (const int*)d_in[1];
    float4*       out  = (float4*)d_out;

    // A: warm L2 with slic + table (36864 threads).
    l2_prefetch<<<144, 256>>>(slic, (const float*)src);

    // B: main gather/stream kernel.
    const int threads = 256;
    const int blocks  = THREADS_TOTAL / threads;   // 32768
    convert2image_l1<<<blocks, threads>>>(src, slic, out);
}

// round 10
// speedup vs baseline: 1.3679x; 1.3679x over previous
#include <cuda_runtime.h>
#include <cstdint>

// out[b,h,w,:] = graph_lstm_output[b, slic[b,h,w]-1, :]
//   graph_lstm_output: [B=4, S=256, C=128] f32   (d_in[0])
//   slic_output:       [B=4, 512, 512] i32       (d_in[1])
//
// R9 post-mortem: prefetch + __ldg(slic) thrashed L1 (82.7%) -> 113us. Revert.
// R3/R5/R8 all pin at 6.0 TB/s / dram_active 76% => suspected HBM write-stream
// ceiling. R10: same R8 structure but 256-bit v8.f32 loads/stores (sm_100+):
// half the LSU instructions, 4 KB/warp in flight per chain, less addr ALU.

static constexpr unsigned V8_PER_BATCH = 1u << 22;        // 2^18 pix * 16 v8
static constexpr int UNROLL = 4;
static constexpr unsigned CHUNK = V8_PER_BATCH / UNROLL;  // 2^20 v8 units
static constexpr unsigned THREADS_TOTAL = 1u << 22;       // 2^24 v8 / 4

__device__ __forceinline__ void ldg_nc_v8(const float* p, float* v)
{
    asm volatile("ld.global.nc.v8.f32 {%0,%1,%2,%3,%4,%5,%6,%7}, [%8];"
                 : "=f"(v[0]), "=f"(v[1]), "=f"(v[2]), "=f"(v[3]),
                   "=f"(v[4]), "=f"(v[5]), "=f"(v[6]), "=f"(v[7])
                 : "l"(p));
}

__device__ __forceinline__ void stg_cs_v8(float* p, const float* v)
{
    asm volatile("st.global.cs.v8.f32 [%0], {%1,%2,%3,%4,%5,%6,%7,%8};"
                 :: "l"(p),
                    "f"(v[0]), "f"(v[1]), "f"(v[2]), "f"(v[3]),
                    "f"(v[4]), "f"(v[5]), "f"(v[6]), "f"(v[7])
                 : "memory");
}

__global__ __launch_bounds__(256)
void convert2image_v8(const float* __restrict__ src,   // [4*256, 128] f32
                      const int*   __restrict__ slic,  // [4, 2^18]
                      float*       __restrict__ out)   // [4, 2^18, 128]
{
    const unsigned t = blockIdx.x * blockDim.x + threadIdx.x;  // [0, 2^22)

    const unsigned b    = t >> 20;             // batch: 2^20 threads per batch
    const unsigned loc  = t & (CHUNK - 1u);    // local v8 base within batch
    const unsigned l16  = loc & 15;            // 16 threads per pixel (32 B ea)

    const int*   sl = slic + (b << 18);
    const float* tb = src  + (b << 15);        // batch table: 256*128 f32
    float*       ob = out  + ((size_t)b << 25);

    // Phase 1: 4 independent slic loads (streamed, keep out of L1).
    const float* rowp[UNROLL];
    #pragma unroll
    for (int i = 0; i < UNROLL; i++) {
        unsigned pix = (loc + (unsigned)i * CHUNK) >> 4;
        int seg = __ldcs(&sl[pix]) - 1;        // 0-based segment
        rowp[i] = tb + (((unsigned)seg) << 7) + (l16 << 3);
    }

    // Phase 2: 4 independent 32 B gathers (batch-local 128 KB table, L1-hot).
    float v[UNROLL][8];
    #pragma unroll
    for (int i = 0; i < UNROLL; i++)
        ldg_nc_v8(rowp[i], v[i]);

    // Phase 3: 4 coalesced 1 KB/warp streaming stores.
    #pragma unroll
    for (int i = 0; i < UNROLL; i++)
        stg_cs_v8(ob + ((size_t)(loc + (unsigned)i * CHUNK) << 3), v[i]);
}

extern "C" void kernel_launch(void* const* d_in, const int* in_sizes, int n_in,
                              void* d_out, int out_size)
{
    const float* src  = (const float*)d_in[0];
    const int*   slic = (const int*)d_in[1];
    float*       out  = (float*)d_out;

    const int threads = 256;
    const int blocks  = THREADS_TOTAL / threads;   // 16384
    convert2image_v8<<<blocks, threads>>>(src, slic, out);
}

// round 12
// speedup vs baseline: 1.3807x; 1.0094x over previous
#include <cuda_runtime.h>
#include <cstdint>

// out[b,h,w,:] = graph_lstm_output[b, slic[b,h,w]-1, :]
//   graph_lstm_output: [B=4, S=256, C=128] f32   (d_in[0])
//   slic_output:       [B=4, 512, 512] i32       (d_in[1])
//
// R10 post-mortem: v8 halved issue rate (19.7->9.5%) but DRAM stayed at
// exactly 6.0 TB/s / 76% -- four different structures all pin there.
// R11 single-variable test: drop the .cs store hint. Default write-back lets
// the 126 MB L2 accumulate full dirty lines and drain dense bursts to the
// memory controller, vs .cs eager streaming. Everything else is R8 verbatim.

static constexpr unsigned F4_PER_BATCH = 1u << 23;        // 2^18 pix * 32 f4
static constexpr int UNROLL = 4;
static constexpr unsigned CHUNK = F4_PER_BATCH / UNROLL;  // 2^21 f4
static constexpr unsigned THREADS_TOTAL = 1u << 23;       // 2^25 f4 / 4

__global__ __launch_bounds__(256)
void convert2image_wb(const float4* __restrict__ src,   // [4*256, 32] float4
                      const int*    __restrict__ slic,  // [4, 2^18]
                      float4*       __restrict__ out)   // [4, 2^18, 32]
{
    const unsigned t = blockIdx.x * blockDim.x + threadIdx.x;  // [0, 2^23)

    const unsigned b    = t >> 21;             // batch: 2^21 threads per batch
    const unsigned loc  = t & (CHUNK - 1u);    // local f4 base within batch
    const unsigned lane = loc & 31;

    const int*    sl = slic + (b << 18);
    const float4* tb = src  + (b << 13);       // this batch's 128 KB table
    float4*       ob = out  + (b << 23);

    // Phase 1: 4 independent slic loads (streamed; keep out of L1 so the
    // 128 KB table stays resident there -- R9's lesson).
    const float4* rowp[UNROLL];
    #pragma unroll
    for (int i = 0; i < UNROLL; i++) {
        unsigned pix = (loc + (unsigned)i * CHUNK) >> 5;
        int seg = __ldcs(&sl[pix]) - 1;        // 0-based segment
        rowp[i] = tb + (((unsigned)seg) << 5); // seg * 32 float4
    }

    // Phase 2: 4 independent gathers from the batch-local L1-hot table.
    float4 v[UNROLL];
    #pragma unroll
    for (int i = 0; i < UNROLL; i++)
        v[i] = __ldg(&rowp[i][lane]);

    // Phase 3: 4 coalesced DEFAULT-policy stores (write-back: let L2
    // accumulate full 128 B lines and drain dense writeback bursts).
    #pragma unroll
    for (int i = 0; i < UNROLL; i++)
        out[(b << 23) + loc + (unsigned)i * CHUNK] = v[i];
    (void)ob;
}

extern "C" void kernel_launch(void* const* d_in, const int* in_sizes, int n_in,
                              void* d_out, int out_size)
{
    const float4* src  = (const float4*)d_in[0];
    const int*    slic = (const int*)d_in[1];
    float4*       out  = (float4*)d_out;

    const int threads = 256;
    const int blocks  = THREADS_TOTAL / threads;   // 32768
    convert2image_wb<<<blocks, threads>>>(src, slic, out);
}